// round 7
// baseline (speedup 1.0000x reference)
#include <cuda_runtime.h>
#include <math.h>

// TwoLayerNetwork: ConstantCurrentLIFEncoder -> LIFCell -> LILinearCell, T=32,
// then max over timesteps and log_softmax.
//
// Constants: DT*TAU_MEM_INV = 0.1 (decay 0.9), DT*TAU_SYN_INV = 0.2 (decay 0.8),
// V_TH = 1.0.
//
// EXACT fast path (proof): v_enc follows v' = 0.9 v + 0.1 x from 0, so
// v_enc <= max_j x_j for all t. A spike needs v_enc > 1.0, so if ALL pixels of
// a row are <= 1.0 that row never spikes downstream: v_out stays 0 and the
// answer is log_softmax(zeros) = -log(10).
//
// Measured model (R2..R6): duration == 12.8MB / ~2.05TB/s + fixed replay
// overhead; invariant under occ/regs/load width. R7 isolates the last knob:
// block count. 4 rows per warp (784 contiguous float4 per warp), grid 256x128.
// Hotness tested per 4-row GROUP; a hot group runs the exact simulator on all
// 4 rows (simulator is exact for cold rows too -> -log 10), so coarser
// granularity is safe for any input.

#define NT 32
#define NPL 25   // neurons per lane (25*32 = 800 >= 784)

__device__ __forceinline__ void simulate_row(
    const float* __restrict__ x,       // row base, 784 floats
    const float* __restrict__ W,       // [10, 784]
    float* __restrict__ orow,          // out row base, 10 floats
    const int lane)
{
    float xs[NPL], ve[NPL], v0[NPL], i0[NPL];
#pragma unroll
    for (int i = 0; i < NPL; i++) {
        const int j = lane + 32 * i;
        xs[i] = (j < 784) ? 0.1f * __ldg(&x[j]) : 0.0f;
        ve[i] = 0.0f; v0[i] = 0.0f; i0[i] = 0.0f;
    }

    float v_out = 0.0f, i_out = 0.0f, vmax = -INFINITY;

#pragma unroll 1
    for (int t = 0; t < NT; t++) {
        unsigned tmask = 0u;
#pragma unroll
        for (int i = 0; i < NPL; i++) {
            // encoder LIF step
            float v = fmaf(ve[i], 0.9f, xs[i]);
            const bool pe = (v > 1.0f);
            const float zef = pe ? 1.0f : 0.0f;
            ve[i] = pe ? 0.0f : v;
            // hidden LIF step (reads old v0, i0)
            const float vd = fmaf(v0[i], 0.9f, 0.1f * i0[i]);
            const bool p0 = (vd > 1.0f);
            v0[i] = p0 ? 0.0f : vd;
            i0[i] = fmaf(i0[i], 0.8f, zef);
            if (p0) tmask |= (1u << i);
        }

        // s[k] = sum_j z0[j] * W[k, j]; zero on spike-free steps.
        float s = 0.0f;
        if (__any_sync(0xffffffffu, tmask != 0u)) {
            float acc[10];
#pragma unroll
            for (int k = 0; k < 10; k++) acc[k] = 0.0f;
            unsigned mm = tmask;
            while (mm) {
                const int i = __ffs(mm) - 1;
                mm &= (mm - 1u);
                const int j = lane + 32 * i;
#pragma unroll
                for (int k = 0; k < 10; k++)
                    acc[k] += __ldg(&W[k * 784 + j]);
            }
#pragma unroll
            for (int k = 0; k < 10; k++) {
#pragma unroll
                for (int off = 16; off; off >>= 1)
                    acc[k] += __shfl_xor_sync(0xffffffffu, acc[k], off);
            }
            s = acc[0];
#pragma unroll
            for (int k = 1; k < 10; k++) s = (lane == k) ? acc[k] : s;
        }

        const float i_jump = i_out + s;
        v_out = fmaf(v_out, 0.9f, 0.1f * i_jump);
        i_out = 0.8f * i_jump;
        vmax = fmaxf(vmax, v_out);
    }

    // log_softmax over the 10 classes held by lanes 0..9
    const float v = (lane < 10) ? vmax : -INFINITY;
    float mred = v;
#pragma unroll
    for (int off = 16; off; off >>= 1)
        mred = fmaxf(mred, __shfl_xor_sync(0xffffffffu, mred, off));
    float e = (lane < 10) ? expf(v - mred) : 0.0f;
    float se = e;
#pragma unroll
    for (int off = 16; off; off >>= 1)
        se += __shfl_xor_sync(0xffffffffu, se, off);

    if (lane < 10)
        orow[lane] = v - mred - logf(se);
}

__global__ __launch_bounds__(128) void snn_kernel(
    const float* __restrict__ image,   // [4096, 784]
    const float* __restrict__ W,       // [10, 784]
    float* __restrict__ out)           // [4096, 10]
{
    const int lane = threadIdx.x & 31;
    const int w = blockIdx.x * 4 + (threadIdx.x >> 5);   // warp id, 0..1023
    const int b0 = w * 4;                                // first of four rows

    // Unconditional early write of the spike-free answer for all 4 rows:
    // one coalesced 40-float contiguous span (out is [4096,10] row-major).
    // Hot groups overwrite below in program order.
    float* og = out + (size_t)b0 * 10;
    og[lane] = -2.302585093f;               // floats [0..32)
    if (lane < 8) og[32 + lane] = -2.302585093f;  // floats [32..40)

    // ---- vectorized group-max scan: 784 contiguous float4 (4 rows) ----
    const float* x = image + (size_t)b0 * 784;
    const float4* x4 = (const float4*)x;

    float m = 0.0f;
#pragma unroll
    for (int i = 0; i < 24; i++) {
        const float4 v = __ldg(&x4[lane + 32 * i]);
        m = fmaxf(m, fmaxf(fmaxf(v.x, v.y), fmaxf(v.z, v.w)));
    }
    if (lane < 16) {   // 784 = 24*32 + 16
        const float4 v = __ldg(&x4[768 + lane]);
        m = fmaxf(m, fmaxf(fmaxf(v.x, v.y), fmaxf(v.z, v.w)));
    }

    // Group provably spike-free -> constants already written, done.
    if (!__any_sync(0xffffffffu, m > 1.0f))
        return;

    // Hot group (rare): run the exact simulator on all 4 rows.
#pragma unroll 1
    for (int r = 0; r < 4; r++)
        simulate_row(x + 784 * r, W, out + (size_t)(b0 + r) * 10, lane);
}

extern "C" void kernel_launch(void* const* d_in, const int* in_sizes, int n_in,
                              void* d_out, int out_size) {
    const float* image = (const float*)d_in[0];  // [4096,1,28,28] fp32
    const float* W     = (const float*)d_in[1];  // [10,784] fp32
    float* out         = (float*)d_out;          // [4096,10] fp32
    (void)in_sizes; (void)n_in; (void)out_size;

    snn_kernel<<<256, 128>>>(image, W, out);
}

// round 8
// speedup vs baseline: 1.0047x; 1.0047x over previous
#include <cuda_runtime.h>
#include <math.h>

// TwoLayerNetwork: ConstantCurrentLIFEncoder -> LIFCell -> LILinearCell, T=32,
// then max over timesteps and log_softmax.
//
// Constants: DT*TAU_MEM_INV = 0.1 (decay 0.9), DT*TAU_SYN_INV = 0.2 (decay 0.8),
// V_TH = 1.0.
//
// EXACT per-row fast path (proof): v_enc follows v' = 0.9 v + 0.1 x from 0, so
// v_enc <= max_j x_j for all t. A spike needs v_enc > 1.0, so if ALL pixels of
// a row are <= 1.0 that row never spikes downstream: v_out stays 0 and the
// answer is log_softmax(zeros) = -log(10).
//
// Measured conclusion (R2..R7 sweep): bench time is 6.6-6.9us for EVERY
// configuration (occ 11-35%, regs 40-128, loads 4B-16B, grid 256-1024,
// 1-4 rows/warp); DRAM pinned at ~2.1TB/s. For a one-shot ~6us kernel the
// duration IS the mandatory 12.8MB read at the short-kernel/low-pstate DRAM
// ceiling. This round: best measured shape (warp-per-row, 1024x128) with
// branchless full-warp scan loads and split max accumulators.

#define NT 32
#define NPL 25   // neurons per lane (25*32 = 800 >= 784)

__global__ __launch_bounds__(128) void snn_kernel(
    const float* __restrict__ image,   // [4096, 784]
    const float* __restrict__ W,       // [10, 784]
    float* __restrict__ out)           // [4096, 10]
{
    const int lane = threadIdx.x & 31;
    const int b = blockIdx.x * 4 + (threadIdx.x >> 5);

    // Unconditional early write of the spike-free answer; hot rows overwrite
    // below in program order (same thread), so the final value is always right.
    if (lane < 10)
        out[(size_t)b * 10 + lane] = -2.302585093f;  // log_softmax(zeros)

    const float* x = image + (size_t)b * 784;
    const float4* x4 = (const float4*)x;   // 196 vec4 per row

    // ---- vectorized row-max scan: 7 full-warp loads (tail clamped) ----
    float ma = 0.0f, mb = 0.0f;
#pragma unroll
    for (int i = 0; i < 6; i += 2) {
        const float4 va = __ldg(&x4[lane + 32 * i]);
        const float4 vb = __ldg(&x4[lane + 32 * (i + 1)]);
        ma = fmaxf(ma, fmaxf(fmaxf(va.x, va.y), fmaxf(va.z, va.w)));
        mb = fmaxf(mb, fmaxf(fmaxf(vb.x, vb.y), fmaxf(vb.z, vb.w)));
    }
    {   // tail: 196 = 6*32 + 4; clamp index so the load is full-warp & in-bounds
        const int j = 192 + ((lane < 4) ? lane : 3);
        const float4 v = __ldg(&x4[j]);
        ma = fmaxf(ma, fmaxf(fmaxf(v.x, v.y), fmaxf(v.z, v.w)));
    }
    const float m = fmaxf(ma, mb);

    // Row provably spike-free -> constant already written, done.
    if (!__any_sync(0xffffffffu, m > 1.0f))
        return;

    // ---- Full general simulation (bit-exact verified R1 path) ----
    float xs[NPL], ve[NPL], v0[NPL], i0[NPL];
#pragma unroll
    for (int i = 0; i < NPL; i++) {
        const int j = lane + 32 * i;
        xs[i] = (j < 784) ? 0.1f * __ldg(&x[j]) : 0.0f;
        ve[i] = 0.0f; v0[i] = 0.0f; i0[i] = 0.0f;
    }

    float v_out = 0.0f, i_out = 0.0f, vmax = -INFINITY;

#pragma unroll 1
    for (int t = 0; t < NT; t++) {
        unsigned tmask = 0u;
#pragma unroll
        for (int i = 0; i < NPL; i++) {
            // encoder LIF step
            float v = fmaf(ve[i], 0.9f, xs[i]);
            const bool pe = (v > 1.0f);
            const float zef = pe ? 1.0f : 0.0f;
            ve[i] = pe ? 0.0f : v;
            // hidden LIF step (reads old v0, i0)
            const float vd = fmaf(v0[i], 0.9f, 0.1f * i0[i]);
            const bool p0 = (vd > 1.0f);
            v0[i] = p0 ? 0.0f : vd;
            i0[i] = fmaf(i0[i], 0.8f, zef);
            if (p0) tmask |= (1u << i);
        }

        // s[k] = sum_j z0[j] * W[k, j]; zero on spike-free steps.
        float s = 0.0f;
        if (__any_sync(0xffffffffu, tmask != 0u)) {
            float acc[10];
#pragma unroll
            for (int k = 0; k < 10; k++) acc[k] = 0.0f;
            unsigned mm = tmask;
            while (mm) {
                const int i = __ffs(mm) - 1;
                mm &= (mm - 1u);
                const int j = lane + 32 * i;
#pragma unroll
                for (int k = 0; k < 10; k++)
                    acc[k] += __ldg(&W[k * 784 + j]);
            }
#pragma unroll
            for (int k = 0; k < 10; k++) {
#pragma unroll
                for (int off = 16; off; off >>= 1)
                    acc[k] += __shfl_xor_sync(0xffffffffu, acc[k], off);
            }
            s = acc[0];
#pragma unroll
            for (int k = 1; k < 10; k++) s = (lane == k) ? acc[k] : s;
        }

        const float i_jump = i_out + s;
        v_out = fmaf(v_out, 0.9f, 0.1f * i_jump);
        i_out = 0.8f * i_jump;
        vmax = fmaxf(vmax, v_out);
    }

    // log_softmax over the 10 classes held by lanes 0..9
    const float v = (lane < 10) ? vmax : -INFINITY;
    float mred = v;
#pragma unroll
    for (int off = 16; off; off >>= 1)
        mred = fmaxf(mred, __shfl_xor_sync(0xffffffffu, mred, off));
    float e = (lane < 10) ? expf(v - mred) : 0.0f;
    float se = e;
#pragma unroll
    for (int off = 16; off; off >>= 1)
        se += __shfl_xor_sync(0xffffffffu, se, off);

    if (lane < 10)
        out[(size_t)b * 10 + lane] = v - mred - logf(se);
}

extern "C" void kernel_launch(void* const* d_in, const int* in_sizes, int n_in,
                              void* d_out, int out_size) {
    const float* image = (const float*)d_in[0];  // [4096,1,28,28] fp32
    const float* W     = (const float*)d_in[1];  // [10,784] fp32
    float* out         = (float*)d_out;          // [4096,10] fp32
    (void)in_sizes; (void)n_in; (void)out_size;

    snn_kernel<<<1024, 128>>>(image, W, out);
}